// round 2
// baseline (speedup 1.0000x reference)
#include <cuda_runtime.h>
#include <cuda_bf16.h>
#include <cstdint>

// Problem constants
#define BT      16384           // B*T = 32*512
#define HDIM    256
#define NCAT    8
#define NCONT   24
#define VPAD    513
#define ODIM    32
#define NEGINF  (-1e30f)

// Output layout (flattened tuple (u, o, c)):
//   u: [BT, 32]            offset 0
//   o: [BT, 32]            offset 524288
//   c: [8, BT, 513]        offset 1048576
#define OFF_O   (BT * ODIM)
#define OFF_C   (2 * BT * ODIM)

// Scratch (static __device__ arrays — no allocation allowed)
__device__ float g_h1[BT * HDIM];                 // after embed/feat
__device__ float g_h [BT * HDIM];                 // after model_W
__device__ unsigned long long g_amax[NCAT * BT];  // packed (key<<32)|(1023-idx)

__constant__ int c_ncols[NCAT] = {513, 513, 257, 257, 129, 129, 65, 65};

// ---------------------------------------------------------------------------
// K0: zero the argmax scratch (must run every launch for determinism)
// ---------------------------------------------------------------------------
__global__ void k_init_amax() {
    int i = blockIdx.x * blockDim.x + threadIdx.x;
    if (i < NCAT * BT) g_amax[i] = 0ULL;
}

// ---------------------------------------------------------------------------
// K1: h1[bt, c] = mean_f embs[f, id_f, c] + sum_j x_cont[j]*feat_W[j,c] + feat_b[c]
// grid = BT blocks, 256 threads
// ---------------------------------------------------------------------------
__global__ void k_embed(const float* __restrict__ x,
                        const float* __restrict__ embs,
                        const float* __restrict__ feat_W,
                        const float* __restrict__ feat_b) {
    int bt = blockIdx.x;
    int c  = threadIdx.x;
    __shared__ float sx[32];
    if (c < 32) sx[c] = x[bt * 32 + c];
    __syncthreads();

    float e = 0.f;
#pragma unroll
    for (int f = 0; f < NCAT; f++) {
        int id = (int)sx[f] + 1;                   // in [0, vocab-1] < VPAD
        e += embs[((size_t)f * VPAD + id) * HDIM + c];
    }
    float acc = feat_b[c] + e * 0.125f;
#pragma unroll
    for (int j = 0; j < NCONT; j++)
        acc += sx[NCAT + j] * feat_W[j * HDIM + c];
    g_h1[(size_t)bt * HDIM + c] = acc;
}

// ---------------------------------------------------------------------------
// Shared GEMM tile shape: BM=128, BN=64, BK=16, 128 threads, 8x8 microtile.
//   thread (tx, ty): tx = tid & 7  -> cols tx*8 .. tx*8+7
//                    ty = tid >> 3 -> rows ty*8 .. ty*8+7
// ---------------------------------------------------------------------------

// K2: g_h = g_h1 @ model_W + model_b   (16384 x 256 x 256)
// grid = (BT/128, 256/64)
__global__ void __launch_bounds__(128)
k_gemm_h(const float* __restrict__ Wm, const float* __restrict__ bm) {
    const int BM = 128, BN = 64, BK = 16;
    __shared__ float As[BK][BM];
    __shared__ float Bs[BK][BN];

    int m0 = blockIdx.x * BM;
    int n0 = blockIdx.y * BN;
    int tid = threadIdx.x;
    int tx = tid & 7, ty = tid >> 3;

    float acc[8][8];
#pragma unroll
    for (int r = 0; r < 8; r++)
#pragma unroll
        for (int j = 0; j < 8; j++) acc[r][j] = 0.f;

    for (int k0 = 0; k0 < HDIM; k0 += BK) {
        // A tile: 128x16 -> As[k][m]; 512 float4, 4 per thread
#pragma unroll
        for (int i = 0; i < 4; i++) {
            int li  = tid + i * 128;        // 0..511
            int row = li >> 2;              // 4 float4 per row
            int kk  = (li & 3) * 4;
            float4 v = *(const float4*)&g_h1[((size_t)(m0 + row)) * HDIM + k0 + kk];
            As[kk + 0][row] = v.x; As[kk + 1][row] = v.y;
            As[kk + 2][row] = v.z; As[kk + 3][row] = v.w;
        }
        // B tile: 16x64 -> 256 float4, 2 per thread
#pragma unroll
        for (int i = 0; i < 2; i++) {
            int li   = tid + i * 128;       // 0..255
            int row  = li >> 4;             // 16 float4 per row
            int col4 = (li & 15) * 4;
            *(float4*)&Bs[row][col4] =
                *(const float4*)&Wm[(size_t)(k0 + row) * HDIM + n0 + col4];
        }
        __syncthreads();
#pragma unroll
        for (int k = 0; k < BK; k++) {
            float4 a0 = *(float4*)&As[k][ty * 8];
            float4 a1 = *(float4*)&As[k][ty * 8 + 4];
            float4 b0 = *(float4*)&Bs[k][tx * 8];
            float4 b1 = *(float4*)&Bs[k][tx * 8 + 4];
            float a[8] = {a0.x, a0.y, a0.z, a0.w, a1.x, a1.y, a1.z, a1.w};
            float b[8] = {b0.x, b0.y, b0.z, b0.w, b1.x, b1.y, b1.z, b1.w};
#pragma unroll
            for (int r = 0; r < 8; r++)
#pragma unroll
                for (int j = 0; j < 8; j++) acc[r][j] += a[r] * b[j];
        }
        __syncthreads();
    }
#pragma unroll
    for (int r = 0; r < 8; r++) {
        int gr = m0 + ty * 8 + r;
        int gc = n0 + tx * 8;
        float4 o0, o1;
        o0.x = acc[r][0] + bm[gc + 0]; o0.y = acc[r][1] + bm[gc + 1];
        o0.z = acc[r][2] + bm[gc + 2]; o0.w = acc[r][3] + bm[gc + 3];
        o1.x = acc[r][4] + bm[gc + 4]; o1.y = acc[r][5] + bm[gc + 5];
        o1.z = acc[r][6] + bm[gc + 6]; o1.w = acc[r][7] + bm[gc + 7];
        *(float4*)&g_h[(size_t)gr * HDIM + gc]     = o0;
        *(float4*)&g_h[(size_t)gr * HDIM + gc + 4] = o1;
    }
}

// ---------------------------------------------------------------------------
// K3: o[bt,:] = h@fco_W + fco_b ;  u[bt,8:32] = (h@fcu_W + fcu_b)[8:32]
// grid = BT blocks, 64 threads
// ---------------------------------------------------------------------------
__global__ void k_heads(const float* __restrict__ fcuW, const float* __restrict__ fcub,
                        const float* __restrict__ fcoW, const float* __restrict__ fcob,
                        float* __restrict__ out) {
    int bt = blockIdx.x;
    int t  = threadIdx.x;
    __shared__ float sh[HDIM];
    for (int i = t; i < HDIM; i += 64) sh[i] = g_h[(size_t)bt * HDIM + i];
    __syncthreads();

    if (t < 32) {
        float s = fcob[t];
#pragma unroll 8
        for (int k = 0; k < HDIM; k++) s += sh[k] * fcoW[k * ODIM + t];
        out[OFF_O + bt * ODIM + t] = s;
    } else {
        int d = t - 32;
        if (d >= NCAT) {
            float s = fcub[d];
#pragma unroll 8
            for (int k = 0; k < HDIM; k++) s += sh[k] * fcuW[k * ODIM + d];
            out[bt * ODIM + d] = s;
        }
    }
}

// ---------------------------------------------------------------------------
// K4: c[f,bt,v] = h @ cat_W[f] + cat_b[f] (masked to -1e30 for v >= vocab+1)
//     + fused per-row argmax via packed u64 atomicMax
// grid = (BT/128 m-tiles, 9 n-tiles, 8 f), 128 threads
// ---------------------------------------------------------------------------
__global__ void __launch_bounds__(128)
k_logits(const float* __restrict__ catW, const float* __restrict__ catb,
         float* __restrict__ out) {
    const int BM = 128, BN = 64, BK = 16;
    int f  = blockIdx.z;
    int ncols = c_ncols[f];
    int m0 = blockIdx.x * BM;
    int n0 = blockIdx.y * BN;
    int tid = threadIdx.x;
    int tx = tid & 7, ty = tid >> 3;

    float* c = out + OFF_C + (size_t)f * BT * VPAD;

    if (n0 >= ncols) {
        // pure fill tile: write -1e30, no compute, no argmax contribution
#pragma unroll
        for (int r = 0; r < 8; r++) {
            int gr = m0 + ty * 8 + r;
#pragma unroll
            for (int j = 0; j < 8; j++) {
                int gc = n0 + tx * 8 + j;
                if (gc < VPAD) c[(size_t)gr * VPAD + gc] = NEGINF;
            }
        }
        return;
    }

    const float* Bmat = catW + (size_t)f * HDIM * VPAD;
    __shared__ float As[BK][BM];
    __shared__ float Bs[BK][BN];
    __shared__ unsigned long long sred[BM];
    if (tid < BM) sred[tid] = 0ULL;   // BM==blockDim.x

    float acc[8][8];
#pragma unroll
    for (int r = 0; r < 8; r++)
#pragma unroll
        for (int j = 0; j < 8; j++) acc[r][j] = 0.f;

    for (int k0 = 0; k0 < HDIM; k0 += BK) {
#pragma unroll
        for (int i = 0; i < 4; i++) {
            int li  = tid + i * 128;
            int row = li >> 2;
            int kk  = (li & 3) * 4;
            float4 v = *(const float4*)&g_h[((size_t)(m0 + row)) * HDIM + k0 + kk];
            As[kk + 0][row] = v.x; As[kk + 1][row] = v.y;
            As[kk + 2][row] = v.z; As[kk + 3][row] = v.w;
        }
#pragma unroll
        for (int i = 0; i < 2; i++) {
            int li   = tid + i * 128;
            int row  = li >> 4;
            int col4 = (li & 15) * 4;
#pragma unroll
            for (int j = 0; j < 4; j++) {
                int gc = n0 + col4 + j;
                Bs[row][col4 + j] = (gc < VPAD)
                    ? Bmat[(size_t)(k0 + row) * VPAD + gc] : 0.f;
            }
        }
        __syncthreads();
#pragma unroll
        for (int k = 0; k < BK; k++) {
            float4 a0 = *(float4*)&As[k][ty * 8];
            float4 a1 = *(float4*)&As[k][ty * 8 + 4];
            float4 b0 = *(float4*)&Bs[k][tx * 8];
            float4 b1 = *(float4*)&Bs[k][tx * 8 + 4];
            float a[8] = {a0.x, a0.y, a0.z, a0.w, a1.x, a1.y, a1.z, a1.w};
            float b[8] = {b0.x, b0.y, b0.z, b0.w, b1.x, b1.y, b1.z, b1.w};
#pragma unroll
            for (int r = 0; r < 8; r++)
#pragma unroll
                for (int j = 0; j < 8; j++) acc[r][j] += a[r] * b[j];
        }
        __syncthreads();
    }

    // epilogue: bias, mask, store c, collect per-row best (packed)
#pragma unroll
    for (int r = 0; r < 8; r++) {
        int gr = m0 + ty * 8 + r;
        unsigned long long best = 0ULL;
#pragma unroll
        for (int j = 0; j < 8; j++) {
            int gc = n0 + tx * 8 + j;
            if (gc >= VPAD) continue;
            float v;
            if (gc < ncols) {
                v = acc[r][j] + catb[f * VPAD + gc];
                unsigned u = __float_as_uint(v);
                unsigned key = (u & 0x80000000u) ? ~u : (u | 0x80000000u);
                unsigned long long p =
                    ((unsigned long long)key << 32) | (unsigned long long)(1023 - gc);
                if (p > best) best = p;
            } else {
                v = NEGINF;
            }
            c[(size_t)gr * VPAD + gc] = v;
        }
        if (best) atomicMax(&sred[ty * 8 + r], best);
    }
    __syncthreads();
    if (tid < BM) {
        unsigned long long b = sred[tid];
        if (b) atomicMax(&g_amax[(size_t)f * BT + m0 + tid], b);
    }
}

// ---------------------------------------------------------------------------
// K5: decode argmax into u[:, :, 0:8]
// ---------------------------------------------------------------------------
__global__ void k_writearg(float* __restrict__ out) {
    int i = blockIdx.x * blockDim.x + threadIdx.x;
    if (i >= NCAT * BT) return;
    int f  = i / BT;
    int bt = i - f * BT;
    unsigned long long p = g_amax[i];
    int idx = 1023 - (int)(p & 0xFFFFFFFFu);
    out[bt * ODIM + f] = (float)idx - 1.0f;
}

// ---------------------------------------------------------------------------
extern "C" void kernel_launch(void* const* d_in, const int* in_sizes, int n_in,
                              void* d_out, int out_size) {
    const float* x       = (const float*)d_in[0];
    const float* embs    = (const float*)d_in[1];
    const float* feat_W  = (const float*)d_in[2];
    const float* feat_b  = (const float*)d_in[3];
    const float* model_W = (const float*)d_in[4];
    const float* model_b = (const float*)d_in[5];
    const float* fcu_W   = (const float*)d_in[6];
    const float* fcu_b   = (const float*)d_in[7];
    const float* fco_W   = (const float*)d_in[8];
    const float* fco_b   = (const float*)d_in[9];
    const float* cat_W   = (const float*)d_in[10];
    const float* cat_b   = (const float*)d_in[11];
    float* out = (float*)d_out;

    k_init_amax<<<(NCAT * BT + 255) / 256, 256>>>();
    k_embed<<<BT, HDIM>>>(x, embs, feat_W, feat_b);
    k_gemm_h<<<dim3(BT / 128, HDIM / 64), 128>>>(model_W, model_b);
    k_heads<<<BT, 64>>>(fcu_W, fcu_b, fco_W, fco_b, out);
    k_logits<<<dim3(BT / 128, (VPAD + 63) / 64, NCAT), 128>>>(cat_W, cat_b, out);
    k_writearg<<<(NCAT * BT + 255) / 256, 256>>>(out);
}

// round 7
// speedup vs baseline: 1.8255x; 1.8255x over previous
#include <cuda_runtime.h>
#include <cuda_bf16.h>
#include <cuda_fp16.h>
#include <cstdint>

// Problem constants
#define BT      16384           // B*T = 32*512
#define HDIM    256
#define NCAT    8
#define NCONT   24
#define VPAD    513
#define ODIM    32
#define NEGINF  (-1e30f)
#define NPAD    576             // padded vocab cols for catWT (max n0+64)

// Output layout (flattened tuple (u, o, c)):
#define OFF_O   (BT * ODIM)
#define OFF_C   (2 * BT * ODIM)

// Scratch (static __device__ arrays — no allocation allowed)
__device__ float g_h1[BT * HDIM];                  // after embed/feat
__device__ float g_h [BT * HDIM];                  // after model_W (fp32)
__device__ __align__(16) __half g_hh[BT * HDIM];   // h split hi (f16)
__device__ __align__(16) __half g_hl[BT * HDIM];   // h split lo (f16)
__device__ __align__(16) __half g_cwh[NCAT * NPAD * HDIM]; // cat_W^T hi [n][k]
__device__ __align__(16) __half g_cwl[NCAT * NPAD * HDIM]; // cat_W^T lo [n][k]
__device__ unsigned long long g_amax[NCAT * BT];   // packed (key<<32)|(1023-idx)

__constant__ int c_ncols[NCAT] = {513, 513, 257, 257, 129, 129, 65, 65};
// 38 computed (f, n0) tiles of 64 cols
__constant__ signed char c_tf[38] = {0,0,0,0,0,0,0,0,0, 1,1,1,1,1,1,1,1,1,
                                     2,2,2,2,2, 3,3,3,3,3, 4,4,4, 5,5,5, 6,6, 7,7};
__constant__ short c_tn[38] = {0,64,128,192,256,320,384,448,512,
                               0,64,128,192,256,320,384,448,512,
                               0,64,128,192,256, 0,64,128,192,256,
                               0,64,128, 0,64,128, 0,64, 0,64};

// ---------------------------------------------------------------------------
// Warp-MMA helpers (baseline PTX, works on .target sm_100)
// ---------------------------------------------------------------------------
__device__ __forceinline__ uint32_t smem_u32(const void* p) {
    uint32_t a;
    asm("{ .reg .u64 t; cvta.to.shared.u64 t, %1; cvt.u32.u64 %0, t; }"
        : "=r"(a) : "l"(p));
    return a;
}

#define LDSM_X4(r0, r1, r2, r3, addr) \
    asm volatile("ldmatrix.sync.aligned.m8n8.x4.shared.b16 {%0,%1,%2,%3}, [%4];" \
        : "=r"(r0), "=r"(r1), "=r"(r2), "=r"(r3) : "r"(addr))

#define MMA16816(c0, c1, c2, c3, a0, a1, a2, a3, b0, b1) \
    asm volatile("mma.sync.aligned.m16n8k16.row.col.f32.f16.f16.f32 " \
        "{%0,%1,%2,%3}, {%4,%5,%6,%7}, {%8,%9}, {%0,%1,%2,%3};" \
        : "+f"(c0), "+f"(c1), "+f"(c2), "+f"(c3) \
        : "r"(a0), "r"(a1), "r"(a2), "r"(a3), "r"(b0), "r"(b1))

// ---------------------------------------------------------------------------
// K0: zero the argmax scratch
// ---------------------------------------------------------------------------
__global__ void k_init_amax() {
    int i = blockIdx.x * blockDim.x + threadIdx.x;
    if (i < NCAT * BT) g_amax[i] = 0ULL;
}

// ---------------------------------------------------------------------------
// K_prep: cat_W [8,256,513] -> transposed padded f16 hi/lo [8,576,256]
// ---------------------------------------------------------------------------
__global__ void k_prep_catw(const float* __restrict__ catW) {
    int n = blockIdx.x, f = blockIdx.y, k = threadIdx.x;
    float v = (n < VPAD) ? catW[((size_t)f * HDIM + k) * VPAD + n] : 0.f;
    __half hi = __float2half_rn(v);
    __half lo = __float2half_rn(v - __half2float(hi));
    size_t o = ((size_t)f * NPAD + n) * HDIM + k;
    g_cwh[o] = hi;
    g_cwl[o] = lo;
}

// ---------------------------------------------------------------------------
// K1: h1 = mean(embs gather) + x_cont @ feat_W + feat_b
// ---------------------------------------------------------------------------
__global__ void k_embed(const float* __restrict__ x,
                        const float* __restrict__ embs,
                        const float* __restrict__ feat_W,
                        const float* __restrict__ feat_b) {
    int bt = blockIdx.x;
    int c  = threadIdx.x;
    __shared__ float sx[32];
    if (c < 32) sx[c] = x[bt * 32 + c];
    __syncthreads();

    float e = 0.f;
#pragma unroll
    for (int f = 0; f < NCAT; f++) {
        int id = (int)sx[f] + 1;
        e += embs[((size_t)f * VPAD + id) * HDIM + c];
    }
    float acc = feat_b[c] + e * 0.125f;
#pragma unroll
    for (int j = 0; j < NCONT; j++)
        acc += sx[NCAT + j] * feat_W[j * HDIM + c];
    g_h1[(size_t)bt * HDIM + c] = acc;
}

// ---------------------------------------------------------------------------
// K2: g_h = g_h1 @ model_W + model_b, plus f16 hi/lo split outputs
// ---------------------------------------------------------------------------
__global__ void __launch_bounds__(128)
k_gemm_h(const float* __restrict__ Wm, const float* __restrict__ bm) {
    const int BM = 128, BN = 64, BK = 16;
    __shared__ float As[BK][BM];
    __shared__ float Bs[BK][BN];

    int m0 = blockIdx.x * BM;
    int n0 = blockIdx.y * BN;
    int tid = threadIdx.x;
    int tx = tid & 7, ty = tid >> 3;

    float acc[8][8];
#pragma unroll
    for (int r = 0; r < 8; r++)
#pragma unroll
        for (int j = 0; j < 8; j++) acc[r][j] = 0.f;

    for (int k0 = 0; k0 < HDIM; k0 += BK) {
#pragma unroll
        for (int i = 0; i < 4; i++) {
            int li  = tid + i * 128;
            int row = li >> 2;
            int kk  = (li & 3) * 4;
            float4 v = *(const float4*)&g_h1[((size_t)(m0 + row)) * HDIM + k0 + kk];
            As[kk + 0][row] = v.x; As[kk + 1][row] = v.y;
            As[kk + 2][row] = v.z; As[kk + 3][row] = v.w;
        }
#pragma unroll
        for (int i = 0; i < 2; i++) {
            int li   = tid + i * 128;
            int row  = li >> 4;
            int col4 = (li & 15) * 4;
            *(float4*)&Bs[row][col4] =
                *(const float4*)&Wm[(size_t)(k0 + row) * HDIM + n0 + col4];
        }
        __syncthreads();
#pragma unroll
        for (int k = 0; k < BK; k++) {
            float4 a0 = *(float4*)&As[k][ty * 8];
            float4 a1 = *(float4*)&As[k][ty * 8 + 4];
            float4 b0 = *(float4*)&Bs[k][tx * 8];
            float4 b1 = *(float4*)&Bs[k][tx * 8 + 4];
            float a[8] = {a0.x, a0.y, a0.z, a0.w, a1.x, a1.y, a1.z, a1.w};
            float b[8] = {b0.x, b0.y, b0.z, b0.w, b1.x, b1.y, b1.z, b1.w};
#pragma unroll
            for (int r = 0; r < 8; r++)
#pragma unroll
                for (int j = 0; j < 8; j++) acc[r][j] += a[r] * b[j];
        }
        __syncthreads();
    }
    union H8 { __half h[8]; uint4 v; };
#pragma unroll
    for (int r = 0; r < 8; r++) {
        int gr = m0 + ty * 8 + r;
        int gc = n0 + tx * 8;
        float o[8];
        H8 hh, hl;
#pragma unroll
        for (int j = 0; j < 8; j++) {
            o[j] = acc[r][j] + bm[gc + j];
            __half hi = __float2half_rn(o[j]);
            hh.h[j] = hi;
            hl.h[j] = __float2half_rn(o[j] - __half2float(hi));
        }
        *(float4*)&g_h[(size_t)gr * HDIM + gc]     = make_float4(o[0], o[1], o[2], o[3]);
        *(float4*)&g_h[(size_t)gr * HDIM + gc + 4] = make_float4(o[4], o[5], o[6], o[7]);
        *(uint4*)&g_hh[(size_t)gr * HDIM + gc] = hh.v;
        *(uint4*)&g_hl[(size_t)gr * HDIM + gc] = hl.v;
    }
}

// ---------------------------------------------------------------------------
// K3: heads as one GEMM: [BT,256] @ [256, 64], cols 0..31 = fcu, 32..63 = fco
// ---------------------------------------------------------------------------
__global__ void __launch_bounds__(128)
k_heads2(const float* __restrict__ fcuW, const float* __restrict__ fcub,
         const float* __restrict__ fcoW, const float* __restrict__ fcob,
         float* __restrict__ out) {
    const int BM = 128, BN = 64, BK = 16;
    __shared__ float As[BK][BM];
    __shared__ float Bs[BK][BN];

    int m0 = blockIdx.x * BM;
    int tid = threadIdx.x;
    int tx = tid & 7, ty = tid >> 3;

    float acc[8][8];
#pragma unroll
    for (int r = 0; r < 8; r++)
#pragma unroll
        for (int j = 0; j < 8; j++) acc[r][j] = 0.f;

    for (int k0 = 0; k0 < HDIM; k0 += BK) {
#pragma unroll
        for (int i = 0; i < 4; i++) {
            int li  = tid + i * 128;
            int row = li >> 2;
            int kk  = (li & 3) * 4;
            float4 v = *(const float4*)&g_h[((size_t)(m0 + row)) * HDIM + k0 + kk];
            As[kk + 0][row] = v.x; As[kk + 1][row] = v.y;
            As[kk + 2][row] = v.z; As[kk + 3][row] = v.w;
        }
#pragma unroll
        for (int i = 0; i < 8; i++) {
            int li  = tid + i * 128;
            int row = li >> 6;
            int col = li & 63;
            Bs[row][col] = (col < 32) ? fcuW[(k0 + row) * ODIM + col]
                                      : fcoW[(k0 + row) * ODIM + col - 32];
        }
        __syncthreads();
#pragma unroll
        for (int k = 0; k < BK; k++) {
            float4 a0 = *(float4*)&As[k][ty * 8];
            float4 a1 = *(float4*)&As[k][ty * 8 + 4];
            float4 b0 = *(float4*)&Bs[k][tx * 8];
            float4 b1 = *(float4*)&Bs[k][tx * 8 + 4];
            float a[8] = {a0.x, a0.y, a0.z, a0.w, a1.x, a1.y, a1.z, a1.w};
            float b[8] = {b0.x, b0.y, b0.z, b0.w, b1.x, b1.y, b1.z, b1.w};
#pragma unroll
            for (int r = 0; r < 8; r++)
#pragma unroll
                for (int j = 0; j < 8; j++) acc[r][j] += a[r] * b[j];
        }
        __syncthreads();
    }
#pragma unroll
    for (int r = 0; r < 8; r++) {
        int gr = m0 + ty * 8 + r;
#pragma unroll
        for (int j = 0; j < 8; j++) {
            int gc = tx * 8 + j;
            if (gc < 32) {
                if (gc >= NCAT) out[gr * ODIM + gc] = acc[r][j] + fcub[gc];
            } else {
                out[OFF_O + gr * ODIM + (gc - 32)] = acc[r][j] + fcob[gc - 32];
            }
        }
    }
}

// ---------------------------------------------------------------------------
// K4: HMMA logits. Block = M128 x N64 tile of feature f; 8 warps (4x2);
// warp tile 32x32; fp16 hi/lo split -> 3 mma products; K in 4 chunks of 64.
// grid (128, 38), 256 threads, dynamic smem.
// B stored [n][k] row-major -> plain ldmatrix (NO .trans) gives the
// col-major B fragment for mma.row.col.
// ---------------------------------------------------------------------------
#define APITCH 72                       // halves per A/B smem row
#define S_AH   0                        // 128*72*2 = 18432
#define S_AL   18432
#define S_BH   36864                    // 64*72*2 = 9216
#define S_BL   46080
#define S_CAT  55296                    // 64 floats bias
#define SMEM_MM (55296 + 256)
// stage (float[128][65] = 33280 B) reuses offset 0 after the MMA loop

__global__ void __launch_bounds__(256)
k_logits_mm(const float* __restrict__ catb, float* __restrict__ out) {
    extern __shared__ char smem[];
    uint32_t sbase = smem_u32(smem);
    int tid = threadIdx.x, wid = tid >> 5, lane = tid & 31;
    int ti = blockIdx.y;
    int f  = c_tf[ti];
    int n0 = c_tn[ti];
    int ncols = c_ncols[f];
    int m0 = blockIdx.x * 128;

    float* scat = (float*)(smem + S_CAT);
    if (tid < 64) {
        int gc = n0 + tid;
        scat[tid] = (gc < ncols) ? catb[f * VPAD + gc] : 0.f;
    }

    const __half* Bh0 = g_cwh + ((size_t)f * NPAD + n0) * HDIM;
    const __half* Bl0 = g_cwl + ((size_t)f * NPAD + n0) * HDIM;

    float acc[2][4][4];
#pragma unroll
    for (int mf = 0; mf < 2; mf++)
#pragma unroll
        for (int nf = 0; nf < 4; nf++)
#pragma unroll
            for (int q = 0; q < 4; q++) acc[mf][nf][q] = 0.f;

    const int rw = (wid & 3) * 32;      // warp row base in tile
    const int cw = (wid >> 2) * 32;     // warp col base in tile

    // per-lane ldmatrix smem addresses (byte offsets within tile rows)
    // A: row = base + (lane&15), col8 = (lane>>4)*8
    uint32_t a_row = (uint32_t)(lane & 15);
    uint32_t a_c8  = (uint32_t)((lane >> 4) * 8);
    // B: row = base + (lane&7) + ((lane>>3)&1)*8, col8 = (lane>>4)*8
    uint32_t b_row = (uint32_t)((lane & 7) + ((lane >> 3) & 1) * 8);
    uint32_t b_c8  = (uint32_t)((lane >> 4) * 8);

    for (int kc = 0; kc < HDIM; kc += 64) {
        // load A chunk: 128 rows x 64 halves (hi, lo): 1024 uint4, 4/thread
#pragma unroll
        for (int i = 0; i < 4; i++) {
            int id = tid + i * 256;
            int r  = id >> 3;
            int c8 = (id & 7) * 8;
            size_t src = (size_t)(m0 + r) * HDIM + kc + c8;
            *(uint4*)(smem + S_AH + (r * APITCH + c8) * 2) = *(const uint4*)(g_hh + src);
            *(uint4*)(smem + S_AL + (r * APITCH + c8) * 2) = *(const uint4*)(g_hl + src);
        }
        // load B chunk: 64 rows x 64 halves (hi, lo): 512 uint4, 2/thread
#pragma unroll
        for (int i = 0; i < 2; i++) {
            int id = tid + i * 256;
            int r  = id >> 3;
            int c8 = (id & 7) * 8;
            size_t src = (size_t)r * HDIM + kc + c8;
            *(uint4*)(smem + S_BH + (r * APITCH + c8) * 2) = *(const uint4*)(Bh0 + src);
            *(uint4*)(smem + S_BL + (r * APITCH + c8) * 2) = *(const uint4*)(Bl0 + src);
        }
        __syncthreads();

#pragma unroll
        for (int ks = 0; ks < 4; ks++) {
            int kk = ks * 16;
            // A fragments hi/lo for 2 m-frags
            uint32_t ah[2][4], al[2][4];
#pragma unroll
            for (int mf = 0; mf < 2; mf++) {
                uint32_t off = ((rw + mf * 16 + a_row) * APITCH + kk + a_c8) * 2;
                LDSM_X4(ah[mf][0], ah[mf][1], ah[mf][2], ah[mf][3], sbase + S_AH + off);
                LDSM_X4(al[mf][0], al[mf][1], al[mf][2], al[mf][3], sbase + S_AL + off);
            }
            // B fragments hi/lo for 4 n-frags (plain x4: r0/r1 = n-groups at k0-7,
            // r2/r3 = n-groups at k8-15)
            uint32_t bh[4][2], bl[4][2];
#pragma unroll
            for (int g = 0; g < 2; g++) {       // n-subtile of 16
                uint32_t off = ((cw + g * 16 + b_row) * APITCH + kk + b_c8) * 2;
                uint32_t r0, r1, r2, r3;
                LDSM_X4(r0, r1, r2, r3, sbase + S_BH + off);
                bh[g * 2 + 0][0] = r0; bh[g * 2 + 0][1] = r2;
                bh[g * 2 + 1][0] = r1; bh[g * 2 + 1][1] = r3;
                LDSM_X4(r0, r1, r2, r3, sbase + S_BL + off);
                bl[g * 2 + 0][0] = r0; bl[g * 2 + 0][1] = r2;
                bl[g * 2 + 1][0] = r1; bl[g * 2 + 1][1] = r3;
            }
#pragma unroll
            for (int mf = 0; mf < 2; mf++)
#pragma unroll
                for (int nf = 0; nf < 4; nf++) {
                    MMA16816(acc[mf][nf][0], acc[mf][nf][1], acc[mf][nf][2], acc[mf][nf][3],
                             ah[mf][0], ah[mf][1], ah[mf][2], ah[mf][3],
                             bh[nf][0], bh[nf][1]);
                    MMA16816(acc[mf][nf][0], acc[mf][nf][1], acc[mf][nf][2], acc[mf][nf][3],
                             ah[mf][0], ah[mf][1], ah[mf][2], ah[mf][3],
                             bl[nf][0], bl[nf][1]);
                    MMA16816(acc[mf][nf][0], acc[mf][nf][1], acc[mf][nf][2], acc[mf][nf][3],
                             al[mf][0], al[mf][1], al[mf][2], al[mf][3],
                             bh[nf][0], bh[nf][1]);
                }
        }
        __syncthreads();
    }

    // Epilogue: bias+mask into stage smem [128][65]
    float* stage = (float*)smem;
    int qr = lane >> 2;           // 0..7
    int qc = (lane & 3) * 2;      // 0,2,4,6
#pragma unroll
    for (int mf = 0; mf < 2; mf++)
#pragma unroll
        for (int nf = 0; nf < 4; nf++) {
            int col = cw + nf * 8 + qc;
            int gc  = n0 + col;
            bool v0 = (gc     < ncols);
            bool v1 = (gc + 1 < ncols);
            int r1 = rw + mf * 16 + qr;
            int r2 = r1 + 8;
            stage[r1 * 65 + col]     = v0 ? acc[mf][nf][0] + scat[col]     : NEGINF;
            stage[r1 * 65 + col + 1] = v1 ? acc[mf][nf][1] + scat[col + 1] : NEGINF;
            stage[r2 * 65 + col]     = v0 ? acc[mf][nf][2] + scat[col]     : NEGINF;
            stage[r2 * 65 + col + 1] = v1 ? acc[mf][nf][3] + scat[col + 1] : NEGINF;
        }
    __syncthreads();

    // Per-row argmax (threads 0..127, conflict-free: pitch 65)
    if (tid < 128) {
        unsigned long long best = 0ULL;
#pragma unroll 8
        for (int col = 0; col < 64; col++) {
            float v = stage[tid * 65 + col];
            unsigned u = __float_as_uint(v);
            unsigned key = (u & 0x80000000u) ? ~u : (u | 0x80000000u);
            unsigned long long pk =
                ((unsigned long long)key << 32) | (unsigned long long)(1023 - (n0 + col));
            if (pk > best) best = pk;
        }
        atomicMax(&g_amax[(size_t)f * BT + m0 + tid], best);
    }

    // Coalesced write-out of c tile
    float* cbase = out + OFF_C + (size_t)f * BT * VPAD;
#pragma unroll
    for (int i = 0; i < 32; i++) {
        int e = tid + i * 256;
        int r = e >> 6;
        int col = e & 63;
        int gc = n0 + col;
        if (gc < VPAD)
            cbase[(size_t)(m0 + r) * VPAD + gc] = stage[r * 65 + col];
    }
}

// ---------------------------------------------------------------------------
// K5: fill invalid region of c with -1e30
// ---------------------------------------------------------------------------
__global__ void k_fill(float* __restrict__ out) {
    int f = blockIdx.y;
    int ncols = c_ncols[f];
    if (ncols >= VPAD) return;
    int r0 = blockIdx.x * 32;
    float* cbase = out + OFF_C + (size_t)f * BT * VPAD;
#pragma unroll 4
    for (int rr = 0; rr < 32; rr++) {
        size_t rowoff = (size_t)(r0 + rr) * VPAD;
        for (int col = ncols + threadIdx.x; col < VPAD; col += blockDim.x)
            cbase[rowoff + col] = NEGINF;
    }
}

// ---------------------------------------------------------------------------
// K6: decode argmax into u[:, :, 0:8]
// ---------------------------------------------------------------------------
__global__ void k_writearg(float* __restrict__ out) {
    int i = blockIdx.x * blockDim.x + threadIdx.x;
    if (i >= NCAT * BT) return;
    int f  = i / BT;
    int bt = i - f * BT;
    unsigned long long p = g_amax[i];
    int idx = 1023 - (int)(p & 0xFFFFFFFFu);
    out[bt * ODIM + f] = (float)idx - 1.0f;
}

// ---------------------------------------------------------------------------
extern "C" void kernel_launch(void* const* d_in, const int* in_sizes, int n_in,
                              void* d_out, int out_size) {
    const float* x       = (const float*)d_in[0];
    const float* embs    = (const float*)d_in[1];
    const float* feat_W  = (const float*)d_in[2];
    const float* feat_b  = (const float*)d_in[3];
    const float* model_W = (const float*)d_in[4];
    const float* model_b = (const float*)d_in[5];
    const float* fcu_W   = (const float*)d_in[6];
    const float* fcu_b   = (const float*)d_in[7];
    const float* fco_W   = (const float*)d_in[8];
    const float* fco_b   = (const float*)d_in[9];
    const float* cat_W   = (const float*)d_in[10];
    const float* cat_b   = (const float*)d_in[11];
    float* out = (float*)d_out;

    cudaFuncSetAttribute(k_logits_mm, cudaFuncAttributeMaxDynamicSharedMemorySize, SMEM_MM);

    k_init_amax<<<(NCAT * BT + 255) / 256, 256>>>();
    k_prep_catw<<<dim3(NPAD, NCAT), 256>>>(cat_W);
    k_embed<<<BT, HDIM>>>(x, embs, feat_W, feat_b);
    k_gemm_h<<<dim3(BT / 128, HDIM / 64), 128>>>(model_W, model_b);
    k_heads2<<<BT / 128, 128>>>(fcu_W, fcu_b, fco_W, fco_b, out);
    k_logits_mm<<<dim3(BT / 128, 38), 256, SMEM_MM>>>(cat_b, out);
    k_fill<<<dim3(BT / 32, NCAT), 256>>>(out);
    k_writearg<<<(NCAT * BT + 255) / 256, 256>>>(out);
}

// round 8
// speedup vs baseline: 2.0871x; 1.1433x over previous
#include <cuda_runtime.h>
#include <cuda_bf16.h>
#include <cuda_fp16.h>
#include <cstdint>

// Problem constants
#define BT      16384           // B*T = 32*512
#define HDIM    256
#define NCAT    8
#define NCONT   24
#define VPAD    513
#define ODIM    32
#define NEGINF  (-1e30f)
#define NPAD    576             // padded vocab cols for catWT

// Output layout (flattened tuple (u, o, c)):
#define OFF_O   (BT * ODIM)
#define OFF_C   (2 * BT * ODIM)

// Scratch (static __device__ arrays — no allocation allowed)
__device__ float g_h1[BT * HDIM];                  // after embed/feat
__device__ float g_h [BT * HDIM];                  // after model_W (fp32)
__device__ __align__(16) __half g_hh[BT * HDIM];   // h split hi (f16)
__device__ __align__(16) __half g_hl[BT * HDIM];   // h split lo (f16)
__device__ __align__(16) __half g_cwh[NCAT * NPAD * HDIM]; // cat_W^T hi [n][k]
__device__ __align__(16) __half g_cwl[NCAT * NPAD * HDIM]; // cat_W^T lo [n][k]
__device__ __align__(16) __half g_fwh[64 * HDIM];  // [fcu|fco]^T hi [j][k]
__device__ __align__(16) __half g_fwl[64 * HDIM];  // [fcu|fco]^T lo [j][k]
__device__ unsigned long long g_amax[NCAT * BT];   // packed (key<<32)|(1023-idx)

__constant__ int c_ncols[NCAT] = {513, 513, 257, 257, 129, 129, 65, 65};
// 30 FULL (f, n0) tiles of 64 valid cols (vocab+1 = k*64+1 for every f)
__constant__ signed char c_tf2[30] = {0,0,0,0,0,0,0,0, 1,1,1,1,1,1,1,1,
                                      2,2,2,2, 3,3,3,3, 4,4, 5,5, 6, 7};
__constant__ short c_tn2[30] = {0,64,128,192,256,320,384,448,
                                0,64,128,192,256,320,384,448,
                                0,64,128,192, 0,64,128,192,
                                0,64, 0,64, 0, 0};
__constant__ short c_colf[8] = {512,512,256,256,128,128,64,64};  // the "+1" col per f

// ---------------------------------------------------------------------------
// Warp-MMA helpers (baseline PTX, works on .target sm_100)
// ---------------------------------------------------------------------------
__device__ __forceinline__ uint32_t smem_u32(const void* p) {
    uint32_t a;
    asm("{ .reg .u64 t; cvta.to.shared.u64 t, %1; cvt.u32.u64 %0, t; }"
        : "=r"(a) : "l"(p));
    return a;
}

#define LDSM_X4(r0, r1, r2, r3, addr) \
    asm volatile("ldmatrix.sync.aligned.m8n8.x4.shared.b16 {%0,%1,%2,%3}, [%4];" \
        : "=r"(r0), "=r"(r1), "=r"(r2), "=r"(r3) : "r"(addr))

#define MMA16816(c0, c1, c2, c3, a0, a1, a2, a3, b0, b1) \
    asm volatile("mma.sync.aligned.m16n8k16.row.col.f32.f16.f16.f32 " \
        "{%0,%1,%2,%3}, {%4,%5,%6,%7}, {%8,%9}, {%0,%1,%2,%3};" \
        : "+f"(c0), "+f"(c1), "+f"(c2), "+f"(c3) \
        : "r"(a0), "r"(a1), "r"(a2), "r"(a3), "r"(b0), "r"(b1))

// ---------------------------------------------------------------------------
// K0: zero the argmax scratch
// ---------------------------------------------------------------------------
__global__ void k_init_amax() {
    int i = blockIdx.x * blockDim.x + threadIdx.x;
    if (i < NCAT * BT) g_amax[i] = 0ULL;
}

// ---------------------------------------------------------------------------
// K_prep: cat_W [8,256,513] -> transposed padded f16 hi/lo [8,576,256]
// ---------------------------------------------------------------------------
__global__ void k_prep_catw(const float* __restrict__ catW) {
    int n = blockIdx.x, f = blockIdx.y, k = threadIdx.x;
    float v = (n < VPAD) ? catW[((size_t)f * HDIM + k) * VPAD + n] : 0.f;
    __half hi = __float2half_rn(v);
    __half lo = __float2half_rn(v - __half2float(hi));
    size_t o = ((size_t)f * NPAD + n) * HDIM + k;
    g_cwh[o] = hi;
    g_cwl[o] = lo;
}

// K_prep2: [fcu_W | fco_W] [256,32]+[256,32] -> transposed f16 hi/lo [64][256]
__global__ void k_prep_fw(const float* __restrict__ fcuW,
                          const float* __restrict__ fcoW) {
    int j = blockIdx.x, k = threadIdx.x;
    float v = (j < 32) ? fcuW[k * ODIM + j] : fcoW[k * ODIM + (j - 32)];
    __half hi = __float2half_rn(v);
    __half lo = __float2half_rn(v - __half2float(hi));
    g_fwh[j * HDIM + k] = hi;
    g_fwl[j * HDIM + k] = lo;
}

// ---------------------------------------------------------------------------
// K1: h1 = mean(embs gather) + x_cont @ feat_W + feat_b
// ---------------------------------------------------------------------------
__global__ void k_embed(const float* __restrict__ x,
                        const float* __restrict__ embs,
                        const float* __restrict__ feat_W,
                        const float* __restrict__ feat_b) {
    int bt = blockIdx.x;
    int c  = threadIdx.x;
    __shared__ float sx[32];
    if (c < 32) sx[c] = x[bt * 32 + c];
    __syncthreads();

    float e = 0.f;
#pragma unroll
    for (int f = 0; f < NCAT; f++) {
        int id = (int)sx[f] + 1;
        e += embs[((size_t)f * VPAD + id) * HDIM + c];
    }
    float acc = feat_b[c] + e * 0.125f;
#pragma unroll
    for (int j = 0; j < NCONT; j++)
        acc += sx[NCAT + j] * feat_W[j * HDIM + c];
    g_h1[(size_t)bt * HDIM + c] = acc;
}

// ---------------------------------------------------------------------------
// K2: g_h = g_h1 @ model_W + model_b (fp32, argmax-critical), + f16 hi/lo split
// ---------------------------------------------------------------------------
__global__ void __launch_bounds__(128)
k_gemm_h(const float* __restrict__ Wm, const float* __restrict__ bm) {
    const int BM = 128, BN = 64, BK = 16;
    __shared__ float As[BK][BM];
    __shared__ float Bs[BK][BN];

    int m0 = blockIdx.x * BM;
    int n0 = blockIdx.y * BN;
    int tid = threadIdx.x;
    int tx = tid & 7, ty = tid >> 3;

    float acc[8][8];
#pragma unroll
    for (int r = 0; r < 8; r++)
#pragma unroll
        for (int j = 0; j < 8; j++) acc[r][j] = 0.f;

    for (int k0 = 0; k0 < HDIM; k0 += BK) {
#pragma unroll
        for (int i = 0; i < 4; i++) {
            int li  = tid + i * 128;
            int row = li >> 2;
            int kk  = (li & 3) * 4;
            float4 v = *(const float4*)&g_h1[((size_t)(m0 + row)) * HDIM + k0 + kk];
            As[kk + 0][row] = v.x; As[kk + 1][row] = v.y;
            As[kk + 2][row] = v.z; As[kk + 3][row] = v.w;
        }
#pragma unroll
        for (int i = 0; i < 2; i++) {
            int li   = tid + i * 128;
            int row  = li >> 4;
            int col4 = (li & 15) * 4;
            *(float4*)&Bs[row][col4] =
                *(const float4*)&Wm[(size_t)(k0 + row) * HDIM + n0 + col4];
        }
        __syncthreads();
#pragma unroll
        for (int k = 0; k < BK; k++) {
            float4 a0 = *(float4*)&As[k][ty * 8];
            float4 a1 = *(float4*)&As[k][ty * 8 + 4];
            float4 b0 = *(float4*)&Bs[k][tx * 8];
            float4 b1 = *(float4*)&Bs[k][tx * 8 + 4];
            float a[8] = {a0.x, a0.y, a0.z, a0.w, a1.x, a1.y, a1.z, a1.w};
            float b[8] = {b0.x, b0.y, b0.z, b0.w, b1.x, b1.y, b1.z, b1.w};
#pragma unroll
            for (int r = 0; r < 8; r++)
#pragma unroll
                for (int j = 0; j < 8; j++) acc[r][j] += a[r] * b[j];
        }
        __syncthreads();
    }
    union H8 { __half h[8]; uint4 v; };
#pragma unroll
    for (int r = 0; r < 8; r++) {
        int gr = m0 + ty * 8 + r;
        int gc = n0 + tx * 8;
        float o[8];
        H8 hh, hl;
#pragma unroll
        for (int j = 0; j < 8; j++) {
            o[j] = acc[r][j] + bm[gc + j];
            __half hi = __float2half_rn(o[j]);
            hh.h[j] = hi;
            hl.h[j] = __float2half_rn(o[j] - __half2float(hi));
        }
        *(float4*)&g_h[(size_t)gr * HDIM + gc]     = make_float4(o[0], o[1], o[2], o[3]);
        *(float4*)&g_h[(size_t)gr * HDIM + gc + 4] = make_float4(o[4], o[5], o[6], o[7]);
        *(uint4*)&g_hh[(size_t)gr * HDIM + gc] = hh.v;
        *(uint4*)&g_hl[(size_t)gr * HDIM + gc] = hl.v;
    }
}

// ---------------------------------------------------------------------------
// Shared smem layout for HMMA kernels
// ---------------------------------------------------------------------------
#define APITCH 72                       // halves per A/B smem row
#define S_AH   0                        // 128*72*2 = 18432
#define S_AL   18432
#define S_BH   36864                    // 64*72*2 = 9216
#define S_BL   46080
#define S_CAT  55296                    // 64 floats bias
#define SMEM_MM (55296 + 256)
// stage (float[128][65] = 33280 B) reuses offset 0 after the MMA loop

// ---------------------------------------------------------------------------
// K3: heads via HMMA split-f16 (no argmax sensitivity; 1e-3 tolerance)
// out cols 0..31 = fcu (write only >=8), 32..63 = fco. grid (128), 256 thr.
// ---------------------------------------------------------------------------
__global__ void __launch_bounds__(256)
k_heads_mm(const float* __restrict__ fcub, const float* __restrict__ fcob,
           float* __restrict__ out) {
    extern __shared__ char smem[];
    uint32_t sbase = smem_u32(smem);
    int tid = threadIdx.x, wid = tid >> 5, lane = tid & 31;
    int m0 = blockIdx.x * 128;

    float acc[2][4][4];
#pragma unroll
    for (int mf = 0; mf < 2; mf++)
#pragma unroll
        for (int nf = 0; nf < 4; nf++)
#pragma unroll
            for (int q = 0; q < 4; q++) acc[mf][nf][q] = 0.f;

    const int rw = (wid & 3) * 32;
    const int cw = (wid >> 2) * 32;
    uint32_t a_row = (uint32_t)(lane & 15);
    uint32_t a_c8  = (uint32_t)((lane >> 4) * 8);
    uint32_t b_row = (uint32_t)((lane & 7) + ((lane >> 3) & 1) * 8);
    uint32_t b_c8  = (uint32_t)((lane >> 4) * 8);

    for (int kc = 0; kc < HDIM; kc += 64) {
#pragma unroll
        for (int i = 0; i < 4; i++) {
            int id = tid + i * 256;
            int r  = id >> 3;
            int c8 = (id & 7) * 8;
            size_t src = (size_t)(m0 + r) * HDIM + kc + c8;
            *(uint4*)(smem + S_AH + (r * APITCH + c8) * 2) = *(const uint4*)(g_hh + src);
            *(uint4*)(smem + S_AL + (r * APITCH + c8) * 2) = *(const uint4*)(g_hl + src);
        }
#pragma unroll
        for (int i = 0; i < 2; i++) {
            int id = tid + i * 256;
            int r  = id >> 3;
            int c8 = (id & 7) * 8;
            size_t src = (size_t)r * HDIM + kc + c8;
            *(uint4*)(smem + S_BH + (r * APITCH + c8) * 2) = *(const uint4*)(g_fwh + src);
            *(uint4*)(smem + S_BL + (r * APITCH + c8) * 2) = *(const uint4*)(g_fwl + src);
        }
        __syncthreads();

#pragma unroll
        for (int ks = 0; ks < 4; ks++) {
            int kk = ks * 16;
            uint32_t ah[2][4], al[2][4];
#pragma unroll
            for (int mf = 0; mf < 2; mf++) {
                uint32_t off = ((rw + mf * 16 + a_row) * APITCH + kk + a_c8) * 2;
                LDSM_X4(ah[mf][0], ah[mf][1], ah[mf][2], ah[mf][3], sbase + S_AH + off);
                LDSM_X4(al[mf][0], al[mf][1], al[mf][2], al[mf][3], sbase + S_AL + off);
            }
            uint32_t bh[4][2], bl[4][2];
#pragma unroll
            for (int g = 0; g < 2; g++) {
                uint32_t off = ((cw + g * 16 + b_row) * APITCH + kk + b_c8) * 2;
                uint32_t r0, r1, r2, r3;
                LDSM_X4(r0, r1, r2, r3, sbase + S_BH + off);
                bh[g * 2 + 0][0] = r0; bh[g * 2 + 0][1] = r2;
                bh[g * 2 + 1][0] = r1; bh[g * 2 + 1][1] = r3;
                LDSM_X4(r0, r1, r2, r3, sbase + S_BL + off);
                bl[g * 2 + 0][0] = r0; bl[g * 2 + 0][1] = r2;
                bl[g * 2 + 1][0] = r1; bl[g * 2 + 1][1] = r3;
            }
#pragma unroll
            for (int mf = 0; mf < 2; mf++)
#pragma unroll
                for (int nf = 0; nf < 4; nf++) {
                    MMA16816(acc[mf][nf][0], acc[mf][nf][1], acc[mf][nf][2], acc[mf][nf][3],
                             ah[mf][0], ah[mf][1], ah[mf][2], ah[mf][3],
                             bh[nf][0], bh[nf][1]);
                    MMA16816(acc[mf][nf][0], acc[mf][nf][1], acc[mf][nf][2], acc[mf][nf][3],
                             ah[mf][0], ah[mf][1], ah[mf][2], ah[mf][3],
                             bl[nf][0], bl[nf][1]);
                    MMA16816(acc[mf][nf][0], acc[mf][nf][1], acc[mf][nf][2], acc[mf][nf][3],
                             al[mf][0], al[mf][1], al[mf][2], al[mf][3],
                             bh[nf][0], bh[nf][1]);
                }
        }
        __syncthreads();
    }

    // direct fragment stores
    int qr = lane >> 2;
    int qc = (lane & 3) * 2;
#pragma unroll
    for (int mf = 0; mf < 2; mf++)
#pragma unroll
        for (int nf = 0; nf < 4; nf++) {
            int col = cw + nf * 8 + qc;
            int r1 = m0 + rw + mf * 16 + qr;
            int r2 = r1 + 8;
#pragma unroll
            for (int e = 0; e < 2; e++) {
                int gc = col + e;
                float bia = (gc < 32) ? fcub[gc] : fcob[gc - 32];
                float v1 = acc[mf][nf][e]     + bia;
                float v2 = acc[mf][nf][2 + e] + bia;
                if (gc < 32) {
                    if (gc >= NCAT) {
                        out[r1 * ODIM + gc] = v1;
                        out[r2 * ODIM + gc] = v2;
                    }
                } else {
                    out[OFF_O + r1 * ODIM + (gc - 32)] = v1;
                    out[OFF_O + r2 * ODIM + (gc - 32)] = v2;
                }
            }
        }
}

// ---------------------------------------------------------------------------
// K4: HMMA logits, 30 FULL tiles only (no masking). grid (128, 30), 256 thr.
// ---------------------------------------------------------------------------
__global__ void __launch_bounds__(256)
k_logits_mm(const float* __restrict__ catb, float* __restrict__ out) {
    extern __shared__ char smem[];
    uint32_t sbase = smem_u32(smem);
    int tid = threadIdx.x, wid = tid >> 5, lane = tid & 31;
    int ti = blockIdx.y;
    int f  = c_tf2[ti];
    int n0 = c_tn2[ti];
    int m0 = blockIdx.x * 128;

    float* scat = (float*)(smem + S_CAT);
    if (tid < 64) scat[tid] = catb[f * VPAD + n0 + tid];

    const __half* Bh0 = g_cwh + ((size_t)f * NPAD + n0) * HDIM;
    const __half* Bl0 = g_cwl + ((size_t)f * NPAD + n0) * HDIM;

    float acc[2][4][4];
#pragma unroll
    for (int mf = 0; mf < 2; mf++)
#pragma unroll
        for (int nf = 0; nf < 4; nf++)
#pragma unroll
            for (int q = 0; q < 4; q++) acc[mf][nf][q] = 0.f;

    const int rw = (wid & 3) * 32;
    const int cw = (wid >> 2) * 32;
    uint32_t a_row = (uint32_t)(lane & 15);
    uint32_t a_c8  = (uint32_t)((lane >> 4) * 8);
    uint32_t b_row = (uint32_t)((lane & 7) + ((lane >> 3) & 1) * 8);
    uint32_t b_c8  = (uint32_t)((lane >> 4) * 8);

    for (int kc = 0; kc < HDIM; kc += 64) {
#pragma unroll
        for (int i = 0; i < 4; i++) {
            int id = tid + i * 256;
            int r  = id >> 3;
            int c8 = (id & 7) * 8;
            size_t src = (size_t)(m0 + r) * HDIM + kc + c8;
            *(uint4*)(smem + S_AH + (r * APITCH + c8) * 2) = *(const uint4*)(g_hh + src);
            *(uint4*)(smem + S_AL + (r * APITCH + c8) * 2) = *(const uint4*)(g_hl + src);
        }
#pragma unroll
        for (int i = 0; i < 2; i++) {
            int id = tid + i * 256;
            int r  = id >> 3;
            int c8 = (id & 7) * 8;
            size_t src = (size_t)r * HDIM + kc + c8;
            *(uint4*)(smem + S_BH + (r * APITCH + c8) * 2) = *(const uint4*)(Bh0 + src);
            *(uint4*)(smem + S_BL + (r * APITCH + c8) * 2) = *(const uint4*)(Bl0 + src);
        }
        __syncthreads();

#pragma unroll
        for (int ks = 0; ks < 4; ks++) {
            int kk = ks * 16;
            uint32_t ah[2][4], al[2][4];
#pragma unroll
            for (int mf = 0; mf < 2; mf++) {
                uint32_t off = ((rw + mf * 16 + a_row) * APITCH + kk + a_c8) * 2;
                LDSM_X4(ah[mf][0], ah[mf][1], ah[mf][2], ah[mf][3], sbase + S_AH + off);
                LDSM_X4(al[mf][0], al[mf][1], al[mf][2], al[mf][3], sbase + S_AL + off);
            }
            uint32_t bh[4][2], bl[4][2];
#pragma unroll
            for (int g = 0; g < 2; g++) {
                uint32_t off = ((cw + g * 16 + b_row) * APITCH + kk + b_c8) * 2;
                uint32_t r0, r1, r2, r3;
                LDSM_X4(r0, r1, r2, r3, sbase + S_BH + off);
                bh[g * 2 + 0][0] = r0; bh[g * 2 + 0][1] = r2;
                bh[g * 2 + 1][0] = r1; bh[g * 2 + 1][1] = r3;
                LDSM_X4(r0, r1, r2, r3, sbase + S_BL + off);
                bl[g * 2 + 0][0] = r0; bl[g * 2 + 0][1] = r2;
                bl[g * 2 + 1][0] = r1; bl[g * 2 + 1][1] = r3;
            }
#pragma unroll
            for (int mf = 0; mf < 2; mf++)
#pragma unroll
                for (int nf = 0; nf < 4; nf++) {
                    MMA16816(acc[mf][nf][0], acc[mf][nf][1], acc[mf][nf][2], acc[mf][nf][3],
                             ah[mf][0], ah[mf][1], ah[mf][2], ah[mf][3],
                             bh[nf][0], bh[nf][1]);
                    MMA16816(acc[mf][nf][0], acc[mf][nf][1], acc[mf][nf][2], acc[mf][nf][3],
                             ah[mf][0], ah[mf][1], ah[mf][2], ah[mf][3],
                             bl[nf][0], bl[nf][1]);
                    MMA16816(acc[mf][nf][0], acc[mf][nf][1], acc[mf][nf][2], acc[mf][nf][3],
                             al[mf][0], al[mf][1], al[mf][2], al[mf][3],
                             bh[nf][0], bh[nf][1]);
                }
        }
        __syncthreads();
    }

    // Epilogue: bias into stage smem [128][65] (all 64 cols valid)
    float* stage = (float*)smem;
    int qr = lane >> 2;
    int qc = (lane & 3) * 2;
#pragma unroll
    for (int mf = 0; mf < 2; mf++)
#pragma unroll
        for (int nf = 0; nf < 4; nf++) {
            int col = cw + nf * 8 + qc;
            int r1 = rw + mf * 16 + qr;
            int r2 = r1 + 8;
            stage[r1 * 65 + col]     = acc[mf][nf][0] + scat[col];
            stage[r1 * 65 + col + 1] = acc[mf][nf][1] + scat[col + 1];
            stage[r2 * 65 + col]     = acc[mf][nf][2] + scat[col];
            stage[r2 * 65 + col + 1] = acc[mf][nf][3] + scat[col + 1];
        }
    __syncthreads();

    // Per-row argmax (threads 0..127, conflict-free: pitch 65)
    if (tid < 128) {
        unsigned long long best = 0ULL;
#pragma unroll 8
        for (int col = 0; col < 64; col++) {
            float v = stage[tid * 65 + col];
            unsigned u = __float_as_uint(v);
            unsigned key = (u & 0x80000000u) ? ~u : (u | 0x80000000u);
            unsigned long long pk =
                ((unsigned long long)key << 32) | (unsigned long long)(1023 - (n0 + col));
            if (pk > best) best = pk;
        }
        atomicMax(&g_amax[(size_t)f * BT + m0 + tid], best);
    }

    // Coalesced write-out of c tile
    float* cbase = out + OFF_C + (size_t)f * BT * VPAD;
#pragma unroll
    for (int i = 0; i < 32; i++) {
        int e = tid + i * 256;
        int r = e >> 6;
        int col = e & 63;
        cbase[(size_t)(m0 + r) * VPAD + n0 + col] = stage[r * 65 + col];
    }
}

// ---------------------------------------------------------------------------
// K4b: the 8 "+1" columns (col = vocab per feature): dot products + argmax
// block = 32 rows x 8 f (256 threads); grid 512
// ---------------------------------------------------------------------------
__global__ void __launch_bounds__(256)
k_extra(const float* __restrict__ catW, const float* __restrict__ catb,
        float* __restrict__ out) {
    __shared__ float sW[8][257];
    __shared__ float sh[32][257];
    int tid = threadIdx.x;
    int row0 = blockIdx.x * 32;

    // load the 8 weight columns (f, col_f) — 2048 scattered reads, L2-hot
#pragma unroll
    for (int i = 0; i < 8; i++) {
        int id = tid + i * 256;
        int f = id >> 8;
        int k = id & 255;
        sW[f][k] = catW[((size_t)f * HDIM + k) * VPAD + c_colf[f]];
    }
    // load 32 h rows coalesced
#pragma unroll
    for (int i = 0; i < 32; i++) {
        int id = tid + i * 256;
        int r = id >> 8;
        int k = id & 255;
        sh[r][k] = g_h[(size_t)(row0 + r) * HDIM + k];
    }
    __syncthreads();

    int f = tid & 7;
    int r = tid >> 3;
    int col = c_colf[f];
    float s = catb[f * VPAD + col];
#pragma unroll 8
    for (int k = 0; k < HDIM; k++) s += sh[r][k] * sW[f][k];

    out[OFF_C + ((size_t)f * BT + row0 + r) * VPAD + col] = s;

    unsigned u = __float_as_uint(s);
    unsigned key = (u & 0x80000000u) ? ~u : (u | 0x80000000u);
    unsigned long long pk =
        ((unsigned long long)key << 32) | (unsigned long long)(1023 - col);
    atomicMax(&g_amax[(size_t)f * BT + row0 + r], pk);
}

// ---------------------------------------------------------------------------
// K5: fill invalid region of c with -1e30
// ---------------------------------------------------------------------------
__global__ void k_fill(float* __restrict__ out) {
    int f = blockIdx.y;
    int ncols = c_ncols[f];
    if (ncols >= VPAD) return;
    int r0 = blockIdx.x * 32;
    float* cbase = out + OFF_C + (size_t)f * BT * VPAD;
#pragma unroll 4
    for (int rr = 0; rr < 32; rr++) {
        size_t rowoff = (size_t)(r0 + rr) * VPAD;
        for (int col = ncols + threadIdx.x; col < VPAD; col += blockDim.x)
            cbase[rowoff + col] = NEGINF;
    }
}

// ---------------------------------------------------------------------------
// K6: decode argmax into u[:, :, 0:8]
// ---------------------------------------------------------------------------
__global__ void k_writearg(float* __restrict__ out) {
    int i = blockIdx.x * blockDim.x + threadIdx.x;
    if (i >= NCAT * BT) return;
    int f  = i / BT;
    int bt = i - f * BT;
    unsigned long long p = g_amax[i];
    int idx = 1023 - (int)(p & 0xFFFFFFFFu);
    out[bt * ODIM + f] = (float)idx - 1.0f;
}

// ---------------------------------------------------------------------------
extern "C" void kernel_launch(void* const* d_in, const int* in_sizes, int n_in,
                              void* d_out, int out_size) {
    const float* x       = (const float*)d_in[0];
    const float* embs    = (const float*)d_in[1];
    const float* feat_W  = (const float*)d_in[2];
    const float* feat_b  = (const float*)d_in[3];
    const float* model_W = (const float*)d_in[4];
    const float* model_b = (const float*)d_in[5];
    const float* fcu_W   = (const float*)d_in[6];
    const float* fcu_b   = (const float*)d_in[7];
    const float* fco_W   = (const float*)d_in[8];
    const float* fco_b   = (const float*)d_in[9];
    const float* cat_W   = (const float*)d_in[10];
    const float* cat_b   = (const float*)d_in[11];
    float* out = (float*)d_out;

    cudaFuncSetAttribute(k_logits_mm, cudaFuncAttributeMaxDynamicSharedMemorySize, SMEM_MM);
    cudaFuncSetAttribute(k_heads_mm, cudaFuncAttributeMaxDynamicSharedMemorySize, SMEM_MM);

    k_init_amax<<<(NCAT * BT + 255) / 256, 256>>>();
    k_prep_catw<<<dim3(NPAD, NCAT), 256>>>(cat_W);
    k_prep_fw<<<64, 256>>>(fcu_W, fco_W);
    k_embed<<<BT, HDIM>>>(x, embs, feat_W, feat_b);
    k_gemm_h<<<dim3(BT / 128, HDIM / 64), 128>>>(model_W, model_b);
    k_heads_mm<<<BT / 128, 256, SMEM_MM>>>(fcu_b, fco_b, out);
    k_logits_mm<<<dim3(BT / 128, 30), 256, SMEM_MM>>>(cat_b, out);
    k_extra<<<BT / 32, 256>>>(cat_W, cat_b, out);
    k_fill<<<dim3(BT / 32, NCAT), 256>>>(out);
    k_writearg<<<(NCAT * BT + 255) / 256, 256>>>(out);
}

// round 9
// speedup vs baseline: 2.3521x; 1.1270x over previous
#include <cuda_runtime.h>
#include <cuda_bf16.h>
#include <cuda_fp16.h>
#include <cstdint>

// Problem constants
#define BT      16384           // B*T = 32*512
#define HDIM    256
#define NCAT    8
#define NCONT   24
#define VPAD    513
#define ODIM    32
#define NEGINF  (-1e30f)
#define NPAD    576             // padded vocab cols for catWT

// Output layout (flattened tuple (u, o, c)):
#define OFF_O   (BT * ODIM)
#define OFF_C   (2 * BT * ODIM)

// Scratch (static __device__ arrays — no allocation allowed)
__device__ __align__(16) __half g_h1h[BT * HDIM];  // h1 split hi
__device__ __align__(16) __half g_h1l[BT * HDIM];  // h1 split lo
__device__ float g_h [BT * HDIM];                  // after model_W (fp32)
__device__ __align__(16) __half g_hh[BT * HDIM];   // h split hi (f16)
__device__ __align__(16) __half g_hl[BT * HDIM];   // h split lo (f16)
__device__ __align__(16) __half g_mwh[HDIM * HDIM]; // model_W^T hi [n][k]
__device__ __align__(16) __half g_mwl[HDIM * HDIM]; // model_W^T lo [n][k]
__device__ __align__(16) __half g_cwh[NCAT * NPAD * HDIM]; // cat_W^T hi [n][k]
__device__ __align__(16) __half g_cwl[NCAT * NPAD * HDIM]; // cat_W^T lo [n][k]
__device__ __align__(16) __half g_fwh[64 * HDIM];  // [fcu|fco]^T hi [j][k]
__device__ __align__(16) __half g_fwl[64 * HDIM];  // [fcu|fco]^T lo [j][k]
__device__ unsigned long long g_amax[NCAT * BT];   // packed (key<<32)|(1023-idx)

__constant__ int c_ncols[NCAT] = {513, 513, 257, 257, 129, 129, 65, 65};
// 30 FULL (f, n0) tiles of 64 valid cols (vocab+1 = k*64+1 for every f)
__constant__ signed char c_tf2[30] = {0,0,0,0,0,0,0,0, 1,1,1,1,1,1,1,1,
                                      2,2,2,2, 3,3,3,3, 4,4, 5,5, 6, 7};
__constant__ short c_tn2[30] = {0,64,128,192,256,320,384,448,
                                0,64,128,192,256,320,384,448,
                                0,64,128,192, 0,64,128,192,
                                0,64, 0,64, 0, 0};
__constant__ short c_colf[8] = {512,512,256,256,128,128,64,64};  // the "+1" col per f

// ---------------------------------------------------------------------------
// Warp-MMA helpers (baseline PTX, works on .target sm_100)
// ---------------------------------------------------------------------------
__device__ __forceinline__ uint32_t smem_u32(const void* p) {
    uint32_t a;
    asm("{ .reg .u64 t; cvta.to.shared.u64 t, %1; cvt.u32.u64 %0, t; }"
        : "=r"(a) : "l"(p));
    return a;
}

#define LDSM_X4(r0, r1, r2, r3, addr) \
    asm volatile("ldmatrix.sync.aligned.m8n8.x4.shared.b16 {%0,%1,%2,%3}, [%4];" \
        : "=r"(r0), "=r"(r1), "=r"(r2), "=r"(r3) : "r"(addr))

#define MMA16816(c0, c1, c2, c3, a0, a1, a2, a3, b0, b1) \
    asm volatile("mma.sync.aligned.m16n8k16.row.col.f32.f16.f16.f32 " \
        "{%0,%1,%2,%3}, {%4,%5,%6,%7}, {%8,%9}, {%0,%1,%2,%3};" \
        : "+f"(c0), "+f"(c1), "+f"(c2), "+f"(c3) \
        : "r"(a0), "r"(a1), "r"(a2), "r"(a3), "r"(b0), "r"(b1))

// ---------------------------------------------------------------------------
// K0: zero the argmax scratch
// ---------------------------------------------------------------------------
__global__ void k_init_amax() {
    int i = blockIdx.x * blockDim.x + threadIdx.x;
    if (i < NCAT * BT) g_amax[i] = 0ULL;
}

// ---------------------------------------------------------------------------
// K_prep: cat_W [8,256,513] -> transposed padded f16 hi/lo [8,576,256]
// smem-tiled transpose: coalesced reads (n-contig) and writes (k-contig).
// block = 32k x 64n tile, 256 threads; grid (8*9, 8)
// ---------------------------------------------------------------------------
__global__ void __launch_bounds__(256)
k_prep_catw(const float* __restrict__ catW) {
    __shared__ float tile[32][65];
    int bt = blockIdx.x;
    int f  = blockIdx.y;
    int k0 = (bt % 8) * 32;
    int n0 = (bt / 8) * 64;
    int tid = threadIdx.x;

    // read: 32 rows (k) x 64 cols (n); thread: n_local = tid&63, k step 4
    int n_local = tid & 63;
    int k_local = tid >> 6;              // 0..3
#pragma unroll
    for (int p = 0; p < 8; p++) {
        int k = k_local + p * 4;
        int n = n0 + n_local;
        tile[k][n_local] = (n < VPAD)
            ? catW[((size_t)f * HDIM + k0 + k) * VPAD + n] : 0.f;
    }
    __syncthreads();

    // write: per n, 32 contiguous k halves; thread: k2 = tid&31, n step 8
    int k2 = tid & 31;
    int nl = tid >> 5;                   // 0..7
#pragma unroll
    for (int p = 0; p < 8; p++) {
        int n = nl + p * 8;
        float v = tile[k2][n];
        __half hi = __float2half_rn(v);
        __half lo = __float2half_rn(v - __half2float(hi));
        size_t o = ((size_t)f * NPAD + n0 + n) * HDIM + k0 + k2;
        g_cwh[o] = hi;
        g_cwl[o] = lo;
    }
}

// K_prep2: [fcu_W | fco_W] -> transposed f16 hi/lo [64][256]
__global__ void k_prep_fw(const float* __restrict__ fcuW,
                          const float* __restrict__ fcoW) {
    int j = blockIdx.x, k = threadIdx.x;
    float v = (j < 32) ? fcuW[k * ODIM + j] : fcoW[k * ODIM + (j - 32)];
    __half hi = __float2half_rn(v);
    __half lo = __float2half_rn(v - __half2float(hi));
    g_fwh[j * HDIM + k] = hi;
    g_fwl[j * HDIM + k] = lo;
}

// K_prep3: model_W [256,256] -> transposed f16 hi/lo [n][k]
__global__ void k_prep_mw(const float* __restrict__ Wm) {
    int n = blockIdx.x, k = threadIdx.x;
    float v = Wm[k * HDIM + n];
    __half hi = __float2half_rn(v);
    __half lo = __float2half_rn(v - __half2float(hi));
    g_mwh[n * HDIM + k] = hi;
    g_mwl[n * HDIM + k] = lo;
}

// ---------------------------------------------------------------------------
// K1: h1 = mean(embs gather) + x_cont @ feat_W + feat_b -> split f16 hi/lo
// 4 tokens per block; feat_W cached in registers. grid BT/4, 256 thr.
// ---------------------------------------------------------------------------
__global__ void __launch_bounds__(256)
k_embed(const float* __restrict__ x,
        const float* __restrict__ embs,
        const float* __restrict__ feat_W,
        const float* __restrict__ feat_b) {
    int c   = threadIdx.x;
    int bt0 = blockIdx.x * 4;
    __shared__ float sx[4][32];
    if (c < 128) {
        int t = c >> 5, j = c & 31;
        sx[t][j] = x[(bt0 + t) * 32 + j];
    }
    __syncthreads();

    float fw[NCONT];
#pragma unroll
    for (int j = 0; j < NCONT; j++) fw[j] = feat_W[j * HDIM + c];
    float fb = feat_b[c];

#pragma unroll
    for (int t = 0; t < 4; t++) {
        float e = 0.f;
#pragma unroll
        for (int f = 0; f < NCAT; f++) {
            int id = (int)sx[t][f] + 1;
            e += embs[((size_t)f * VPAD + id) * HDIM + c];
        }
        float acc = fb + e * 0.125f;
#pragma unroll
        for (int j = 0; j < NCONT; j++)
            acc += sx[t][NCAT + j] * fw[j];
        __half hi = __float2half_rn(acc);
        __half lo = __float2half_rn(acc - __half2float(hi));
        g_h1h[(size_t)(bt0 + t) * HDIM + c] = hi;
        g_h1l[(size_t)(bt0 + t) * HDIM + c] = lo;
    }
}

// ---------------------------------------------------------------------------
// Shared smem layout for HMMA kernels
// ---------------------------------------------------------------------------
#define APITCH 72                       // halves per A/B smem row
#define S_AH   0                        // 128*72*2 = 18432
#define S_AL   18432
#define S_BH   36864                    // 64*72*2 = 9216
#define S_BL   46080
#define S_CAT  55296                    // 64 floats bias
#define SMEM_MM (55296 + 256)
// stage (float[128][65] = 33280 B) reuses offset 0 after the MMA loop

// ---------------------------------------------------------------------------
// HMMA core: computes 128x64 tile of A@B^T (split-f16, 3 products).
// A hi/lo from Ah/Al (row-major [*, 256]); B hi/lo from Bh0/Bl0 ([n][k]).
// Result left in acc[2][4][4]; fragment owner: rows rw+mf*16+{qr, qr+8},
// cols cw+nf*8+qc{,+1}.
// ---------------------------------------------------------------------------
__device__ __forceinline__ void hmma_tile_128x64(
    char* smem, uint32_t sbase, int tid, int wid, int lane,
    const __half* __restrict__ Ah, const __half* __restrict__ Al, int m0,
    const __half* __restrict__ Bh0, const __half* __restrict__ Bl0,
    float acc[2][4][4])
{
    const int rw = (wid & 3) * 32;
    const int cw = (wid >> 2) * 32;
    uint32_t a_row = (uint32_t)(lane & 15);
    uint32_t a_c8  = (uint32_t)((lane >> 4) * 8);
    uint32_t b_row = (uint32_t)((lane & 7) + ((lane >> 3) & 1) * 8);
    uint32_t b_c8  = (uint32_t)((lane >> 4) * 8);

    for (int kc = 0; kc < HDIM; kc += 64) {
#pragma unroll
        for (int i = 0; i < 4; i++) {
            int id = tid + i * 256;
            int r  = id >> 3;
            int c8 = (id & 7) * 8;
            size_t src = (size_t)(m0 + r) * HDIM + kc + c8;
            *(uint4*)(smem + S_AH + (r * APITCH + c8) * 2) = *(const uint4*)(Ah + src);
            *(uint4*)(smem + S_AL + (r * APITCH + c8) * 2) = *(const uint4*)(Al + src);
        }
#pragma unroll
        for (int i = 0; i < 2; i++) {
            int id = tid + i * 256;
            int r  = id >> 3;
            int c8 = (id & 7) * 8;
            size_t src = (size_t)r * HDIM + kc + c8;
            *(uint4*)(smem + S_BH + (r * APITCH + c8) * 2) = *(const uint4*)(Bh0 + src);
            *(uint4*)(smem + S_BL + (r * APITCH + c8) * 2) = *(const uint4*)(Bl0 + src);
        }
        __syncthreads();

#pragma unroll
        for (int ks = 0; ks < 4; ks++) {
            int kk = ks * 16;
            uint32_t ah[2][4], al[2][4];
#pragma unroll
            for (int mf = 0; mf < 2; mf++) {
                uint32_t off = ((rw + mf * 16 + a_row) * APITCH + kk + a_c8) * 2;
                LDSM_X4(ah[mf][0], ah[mf][1], ah[mf][2], ah[mf][3], sbase + S_AH + off);
                LDSM_X4(al[mf][0], al[mf][1], al[mf][2], al[mf][3], sbase + S_AL + off);
            }
            uint32_t bh[4][2], bl[4][2];
#pragma unroll
            for (int g = 0; g < 2; g++) {
                uint32_t off = ((cw + g * 16 + b_row) * APITCH + kk + b_c8) * 2;
                uint32_t r0, r1, r2, r3;
                LDSM_X4(r0, r1, r2, r3, sbase + S_BH + off);
                bh[g * 2 + 0][0] = r0; bh[g * 2 + 0][1] = r2;
                bh[g * 2 + 1][0] = r1; bh[g * 2 + 1][1] = r3;
                LDSM_X4(r0, r1, r2, r3, sbase + S_BL + off);
                bl[g * 2 + 0][0] = r0; bl[g * 2 + 0][1] = r2;
                bl[g * 2 + 1][0] = r1; bl[g * 2 + 1][1] = r3;
            }
#pragma unroll
            for (int mf = 0; mf < 2; mf++)
#pragma unroll
                for (int nf = 0; nf < 4; nf++) {
                    MMA16816(acc[mf][nf][0], acc[mf][nf][1], acc[mf][nf][2], acc[mf][nf][3],
                             ah[mf][0], ah[mf][1], ah[mf][2], ah[mf][3],
                             bh[nf][0], bh[nf][1]);
                    MMA16816(acc[mf][nf][0], acc[mf][nf][1], acc[mf][nf][2], acc[mf][nf][3],
                             ah[mf][0], ah[mf][1], ah[mf][2], ah[mf][3],
                             bl[nf][0], bl[nf][1]);
                    MMA16816(acc[mf][nf][0], acc[mf][nf][1], acc[mf][nf][2], acc[mf][nf][3],
                             al[mf][0], al[mf][1], al[mf][2], al[mf][3],
                             bh[nf][0], bh[nf][1]);
                }
        }
        __syncthreads();
    }
}

// ---------------------------------------------------------------------------
// K2: g_h = h1 @ model_W + model_b via HMMA split-f16; also emits h hi/lo.
// grid (128, 4), 256 thr, SMEM_MM.
// ---------------------------------------------------------------------------
__global__ void __launch_bounds__(256)
k_gemmh_mm(const float* __restrict__ bm) {
    extern __shared__ char smem[];
    uint32_t sbase = smem_u32(smem);
    int tid = threadIdx.x, wid = tid >> 5, lane = tid & 31;
    int m0 = blockIdx.x * 128;
    int n0 = blockIdx.y * 64;

    float* scat = (float*)(smem + S_CAT);
    if (tid < 64) scat[tid] = bm[n0 + tid];

    float acc[2][4][4];
#pragma unroll
    for (int mf = 0; mf < 2; mf++)
#pragma unroll
        for (int nf = 0; nf < 4; nf++)
#pragma unroll
            for (int q = 0; q < 4; q++) acc[mf][nf][q] = 0.f;

    hmma_tile_128x64(smem, sbase, tid, wid, lane,
                     g_h1h, g_h1l, m0,
                     g_mwh + (size_t)n0 * HDIM, g_mwl + (size_t)n0 * HDIM, acc);

    // stage with bias
    float* stage = (float*)smem;
    const int rw = (wid & 3) * 32;
    const int cw = (wid >> 2) * 32;
    int qr = lane >> 2;
    int qc = (lane & 3) * 2;
#pragma unroll
    for (int mf = 0; mf < 2; mf++)
#pragma unroll
        for (int nf = 0; nf < 4; nf++) {
            int col = cw + nf * 8 + qc;
            int r1 = rw + mf * 16 + qr;
            int r2 = r1 + 8;
            stage[r1 * 65 + col]     = acc[mf][nf][0] + scat[col];
            stage[r1 * 65 + col + 1] = acc[mf][nf][1] + scat[col + 1];
            stage[r2 * 65 + col]     = acc[mf][nf][2] + scat[col];
            stage[r2 * 65 + col + 1] = acc[mf][nf][3] + scat[col + 1];
        }
    __syncthreads();

    // coalesced write: fp32 h + f16 hi/lo split
#pragma unroll
    for (int i = 0; i < 32; i++) {
        int e = tid + i * 256;
        int r = e >> 6;
        int col = e & 63;
        float v = stage[r * 65 + col];
        size_t o = (size_t)(m0 + r) * HDIM + n0 + col;
        g_h[o] = v;
        __half hi = __float2half_rn(v);
        g_hh[o] = hi;
        g_hl[o] = __float2half_rn(v - __half2float(hi));
    }
}

// ---------------------------------------------------------------------------
// K3: heads via HMMA split-f16. grid (128), 256 thr.
// ---------------------------------------------------------------------------
__global__ void __launch_bounds__(256)
k_heads_mm(const float* __restrict__ fcub, const float* __restrict__ fcob,
           float* __restrict__ out) {
    extern __shared__ char smem[];
    uint32_t sbase = smem_u32(smem);
    int tid = threadIdx.x, wid = tid >> 5, lane = tid & 31;
    int m0 = blockIdx.x * 128;

    float acc[2][4][4];
#pragma unroll
    for (int mf = 0; mf < 2; mf++)
#pragma unroll
        for (int nf = 0; nf < 4; nf++)
#pragma unroll
            for (int q = 0; q < 4; q++) acc[mf][nf][q] = 0.f;

    hmma_tile_128x64(smem, sbase, tid, wid, lane,
                     g_hh, g_hl, m0, g_fwh, g_fwl, acc);

    const int rw = (wid & 3) * 32;
    const int cw = (wid >> 2) * 32;
    int qr = lane >> 2;
    int qc = (lane & 3) * 2;
#pragma unroll
    for (int mf = 0; mf < 2; mf++)
#pragma unroll
        for (int nf = 0; nf < 4; nf++) {
            int col = cw + nf * 8 + qc;
            int r1 = m0 + rw + mf * 16 + qr;
            int r2 = r1 + 8;
#pragma unroll
            for (int e = 0; e < 2; e++) {
                int gc = col + e;
                float bia = (gc < 32) ? fcub[gc] : fcob[gc - 32];
                float v1 = acc[mf][nf][e]     + bia;
                float v2 = acc[mf][nf][2 + e] + bia;
                if (gc < 32) {
                    if (gc >= NCAT) {
                        out[r1 * ODIM + gc] = v1;
                        out[r2 * ODIM + gc] = v2;
                    }
                } else {
                    out[OFF_O + r1 * ODIM + (gc - 32)] = v1;
                    out[OFF_O + r2 * ODIM + (gc - 32)] = v2;
                }
            }
        }
}

// ---------------------------------------------------------------------------
// K4: HMMA logits, 30 FULL tiles. grid (128, 30), 256 thr.
// ---------------------------------------------------------------------------
__global__ void __launch_bounds__(256)
k_logits_mm(const float* __restrict__ catb, float* __restrict__ out) {
    extern __shared__ char smem[];
    uint32_t sbase = smem_u32(smem);
    int tid = threadIdx.x, wid = tid >> 5, lane = tid & 31;
    int ti = blockIdx.y;
    int f  = c_tf2[ti];
    int n0 = c_tn2[ti];
    int m0 = blockIdx.x * 128;

    float* scat = (float*)(smem + S_CAT);
    if (tid < 64) scat[tid] = catb[f * VPAD + n0 + tid];

    float acc[2][4][4];
#pragma unroll
    for (int mf = 0; mf < 2; mf++)
#pragma unroll
        for (int nf = 0; nf < 4; nf++)
#pragma unroll
            for (int q = 0; q < 4; q++) acc[mf][nf][q] = 0.f;

    hmma_tile_128x64(smem, sbase, tid, wid, lane,
                     g_hh, g_hl, m0,
                     g_cwh + ((size_t)f * NPAD + n0) * HDIM,
                     g_cwl + ((size_t)f * NPAD + n0) * HDIM, acc);

    float* stage = (float*)smem;
    const int rw = (wid & 3) * 32;
    const int cw = (wid >> 2) * 32;
    int qr = lane >> 2;
    int qc = (lane & 3) * 2;
#pragma unroll
    for (int mf = 0; mf < 2; mf++)
#pragma unroll
        for (int nf = 0; nf < 4; nf++) {
            int col = cw + nf * 8 + qc;
            int r1 = rw + mf * 16 + qr;
            int r2 = r1 + 8;
            stage[r1 * 65 + col]     = acc[mf][nf][0] + scat[col];
            stage[r1 * 65 + col + 1] = acc[mf][nf][1] + scat[col + 1];
            stage[r2 * 65 + col]     = acc[mf][nf][2] + scat[col];
            stage[r2 * 65 + col + 1] = acc[mf][nf][3] + scat[col + 1];
        }
    __syncthreads();

    // Per-row argmax (threads 0..127, conflict-free: pitch 65)
    if (tid < 128) {
        unsigned long long best = 0ULL;
#pragma unroll 8
        for (int col = 0; col < 64; col++) {
            float v = stage[tid * 65 + col];
            unsigned u = __float_as_uint(v);
            unsigned key = (u & 0x80000000u) ? ~u : (u | 0x80000000u);
            unsigned long long pk =
                ((unsigned long long)key << 32) | (unsigned long long)(1023 - (n0 + col));
            if (pk > best) best = pk;
        }
        atomicMax(&g_amax[(size_t)f * BT + m0 + tid], best);
    }

    // Coalesced write-out of c tile
    float* cbase = out + OFF_C + (size_t)f * BT * VPAD;
#pragma unroll
    for (int i = 0; i < 32; i++) {
        int e = tid + i * 256;
        int r = e >> 6;
        int col = e & 63;
        cbase[(size_t)(m0 + r) * VPAD + n0 + col] = stage[r * 65 + col];
    }
}

// ---------------------------------------------------------------------------
// K4b: the 8 "+1" columns: dot products + argmax. block 32 rows x 8 f.
// ---------------------------------------------------------------------------
__global__ void __launch_bounds__(256)
k_extra(const float* __restrict__ catW, const float* __restrict__ catb,
        float* __restrict__ out) {
    __shared__ float sW[8][257];
    __shared__ float sh[32][257];
    int tid = threadIdx.x;
    int row0 = blockIdx.x * 32;

#pragma unroll
    for (int i = 0; i < 8; i++) {
        int id = tid + i * 256;
        int f = id >> 8;
        int k = id & 255;
        sW[f][k] = catW[((size_t)f * HDIM + k) * VPAD + c_colf[f]];
    }
#pragma unroll
    for (int i = 0; i < 32; i++) {
        int id = tid + i * 256;
        int r = id >> 8;
        int k = id & 255;
        sh[r][k] = g_h[(size_t)(row0 + r) * HDIM + k];
    }
    __syncthreads();

    int f = tid & 7;
    int r = tid >> 3;
    int col = c_colf[f];
    float s = catb[f * VPAD + col];
#pragma unroll 8
    for (int k = 0; k < HDIM; k++) s += sh[r][k] * sW[f][k];

    out[OFF_C + ((size_t)f * BT + row0 + r) * VPAD + col] = s;

    unsigned u = __float_as_uint(s);
    unsigned key = (u & 0x80000000u) ? ~u : (u | 0x80000000u);
    unsigned long long pk =
        ((unsigned long long)key << 32) | (unsigned long long)(1023 - col);
    atomicMax(&g_amax[(size_t)f * BT + row0 + r], pk);
}

// ---------------------------------------------------------------------------
// K5: fill invalid region of c with -1e30
// ---------------------------------------------------------------------------
__global__ void k_fill(float* __restrict__ out) {
    int f = blockIdx.y;
    int ncols = c_ncols[f];
    if (ncols >= VPAD) return;
    int r0 = blockIdx.x * 32;
    float* cbase = out + OFF_C + (size_t)f * BT * VPAD;
#pragma unroll 4
    for (int rr = 0; rr < 32; rr++) {
        size_t rowoff = (size_t)(r0 + rr) * VPAD;
        for (int col = ncols + threadIdx.x; col < VPAD; col += blockDim.x)
            cbase[rowoff + col] = NEGINF;
    }
}

// ---------------------------------------------------------------------------
// K6: decode argmax into u[:, :, 0:8]
// ---------------------------------------------------------------------------
__global__ void k_writearg(float* __restrict__ out) {
    int i = blockIdx.x * blockDim.x + threadIdx.x;
    if (i >= NCAT * BT) return;
    int f  = i / BT;
    int bt = i - f * BT;
    unsigned long long p = g_amax[i];
    int idx = 1023 - (int)(p & 0xFFFFFFFFu);
    out[bt * ODIM + f] = (float)idx - 1.0f;
}

// ---------------------------------------------------------------------------
extern "C" void kernel_launch(void* const* d_in, const int* in_sizes, int n_in,
                              void* d_out, int out_size) {
    const float* x       = (const float*)d_in[0];
    const float* embs    = (const float*)d_in[1];
    const float* feat_W  = (const float*)d_in[2];
    const float* feat_b  = (const float*)d_in[3];
    const float* model_W = (const float*)d_in[4];
    const float* model_b = (const float*)d_in[5];
    const float* fcu_W   = (const float*)d_in[6];
    const float* fcu_b   = (const float*)d_in[7];
    const float* fco_W   = (const float*)d_in[8];
    const float* fco_b   = (const float*)d_in[9];
    const float* cat_W   = (const float*)d_in[10];
    const float* cat_b   = (const float*)d_in[11];
    float* out = (float*)d_out;

    cudaFuncSetAttribute(k_logits_mm, cudaFuncAttributeMaxDynamicSharedMemorySize, SMEM_MM);
    cudaFuncSetAttribute(k_heads_mm, cudaFuncAttributeMaxDynamicSharedMemorySize, SMEM_MM);
    cudaFuncSetAttribute(k_gemmh_mm, cudaFuncAttributeMaxDynamicSharedMemorySize, SMEM_MM);

    k_init_amax<<<(NCAT * BT + 255) / 256, 256>>>();
    k_prep_catw<<<dim3(72, NCAT), 256>>>(cat_W);
    k_prep_fw<<<64, 256>>>(fcu_W, fco_W);
    k_prep_mw<<<HDIM, HDIM>>>(model_W);
    k_embed<<<BT / 4, 256>>>(x, embs, feat_W, feat_b);
    k_gemmh_mm<<<dim3(BT / 128, 4), 256, SMEM_MM>>>(model_b);
    k_heads_mm<<<BT / 128, 256, SMEM_MM>>>(fcu_b, fco_b, out);
    k_logits_mm<<<dim3(BT / 128, 30), 256, SMEM_MM>>>(cat_b, out);
    k_extra<<<BT / 32, 256>>>(cat_W, cat_b, out);
    k_fill<<<dim3(BT / 32, NCAT), 256>>>(out);
    k_writearg<<<(NCAT * BT + 255) / 256, 256>>>(out);
}